// round 11
// baseline (speedup 1.0000x reference)
#include <cuda_runtime.h>
#include <cstdint>

#define B 8
#define C 128
#define H 256
#define W 256
#define HW (H*W)        // 65536
#define HW4 (HW/4)      // 16384

#define NPOOL 256        // pool blocks per batch (64 f4-pixels x 4 ch-groups)
#define NMUL  4096       // mul blocks per batch (2 float4 per thread)
#define NCONV 64         // conv blocks per batch (64x16 tiles)

__device__ float g_pooled[B * HW];
__device__ float g_attn[B * HW];
__device__ int   g_pool_done[B];

__global__ void reset_kernel() {
    #pragma unroll
    for (int i = 0; i < B; ++i) g_pool_done[i] = 0;
}

// ---------------------------------------------------------------------------
// One launch per pipeline step. Grid layout (role by blockIdx range):
//   [0, nPool)              pool(b_pool):  reads x_{b+1} -> L2-resident
//   [nPool, nPool+nMul)     mul(b_mul):    out = x * attn, x reads hit L2
//   [nPool+nMul, ...)       conv(b_pool):  spins until pool(b_pool) done
// Pool blocks are first in the grid -> scheduled in wave 1; conv blocks are
// last and spin briefly. mul(b) depends only on PREVIOUS launch's conv(b).
// ---------------------------------------------------------------------------
__global__ void __launch_bounds__(256) step_kernel(
        const float* __restrict__ x, float* __restrict__ out,
        const float* __restrict__ cw, const float* __restrict__ cb,
        int b_pool, int b_mul, int nPool, int nMul)
{
    const int bid = blockIdx.x;
    const int tid = threadIdx.x;

    if (bid < nPool) {
        // ---------------- pool role: batch b_pool ----------------
        __shared__ float4 red[256];
        const int grp = tid >> 6;          // 0..3 (32 channels each)
        const int pix = tid & 63;
        const int hw4 = bid * 64 + pix;
        const float4* p = reinterpret_cast<const float4*>(x)
                          + ((size_t)b_pool * C + (size_t)grp * 32) * HW4 + hw4;
        float4 m = p[0];
        #pragma unroll 8
        for (int c = 1; c < 32; ++c) {
            float4 v = p[(size_t)c * HW4];
            m.x = fmaxf(m.x, v.x);
            m.y = fmaxf(m.y, v.y);
            m.z = fmaxf(m.z, v.z);
            m.w = fmaxf(m.w, v.w);
        }
        red[tid] = m;
        __syncthreads();
        if (grp == 0) {
            float4 a  = red[pix];
            float4 b1 = red[64 + pix];
            float4 c1 = red[128 + pix];
            float4 d1 = red[192 + pix];
            a.x = fmaxf(fmaxf(a.x, b1.x), fmaxf(c1.x, d1.x));
            a.y = fmaxf(fmaxf(a.y, b1.y), fmaxf(c1.y, d1.y));
            a.z = fmaxf(fmaxf(a.z, b1.z), fmaxf(c1.z, d1.z));
            a.w = fmaxf(fmaxf(a.w, b1.w), fmaxf(c1.w, d1.w));
            reinterpret_cast<float4*>(g_pooled)[(size_t)b_pool * HW4 + hw4] = a;
        }
        __syncthreads();
        if (tid == 0) { __threadfence(); atomicAdd(&g_pool_done[b_pool], 1); }
    } else if (bid < nPool + nMul) {
        // ---------------- mul role: batch b_mul (2 float4 per thread) ------
        const int u = bid - nPool;
        #pragma unroll
        for (int h = 0; h < 2; ++h) {
            const int i   = (u * 256 + tid) + h * (NMUL * 256);  // < 2^21
            const int hw4 = i & (HW4 - 1);
            const int c   = i >> 14;
            const size_t gi = ((size_t)b_mul * C + c) * HW4 + hw4;
            float4 a = __ldg(reinterpret_cast<const float4*>(g_attn)
                             + (size_t)b_mul * HW4 + hw4);
            float4 v = __ldcs(reinterpret_cast<const float4*>(x) + gi);
            v.x *= a.x; v.y *= a.y; v.z *= a.z; v.w *= a.w;
            __stcs(reinterpret_cast<float4*>(out) + gi, v);
        }
    } else {
        // ---------------- conv role: batch b_pool (waits on pool) ----------
        const int u   = bid - nPool - nMul;   // 0..63
        const int tx0 = (u & 3) * 64;
        const int ty0 = (u >> 2) * 16;

        if (tid == 0) {
            while (*(volatile int*)&g_pool_done[b_pool] < NPOOL)
                __nanosleep(64);
            __threadfence();
        }
        __syncthreads();

        __shared__ float s[22][72];
        const float* pb = g_pooled + b_pool * HW;
        for (int i = tid; i < 22 * 70; i += 256) {
            int ly = i / 70;
            int lx = i - ly * 70;
            int gy = ty0 + ly - 3;
            int gx = tx0 + lx - 3;
            float v = 0.0f;
            if (gy >= 0 && gy < H && gx >= 0 && gx < W) v = pb[gy * W + gx];
            s[ly][lx] = v;
        }
        __syncthreads();

        const int lx  = tid & 63;
        const int ly0 = tid >> 6;          // 0..3
        const float bias = __ldg(&cb[0]);
        #pragma unroll
        for (int r = 0; r < 16; r += 4) {
            const int ly = ly0 + r;
            float acc = bias;
            #pragma unroll
            for (int i = 0; i < 7; ++i)
                #pragma unroll
                for (int j = 0; j < 7; ++j)
                    acc = fmaf(s[ly + i][lx + j], __ldg(&cw[i * 7 + j]), acc);
            float sg = 1.0f / (1.0f + __expf(-acc));
            g_attn[b_pool * HW + (ty0 + ly) * W + tx0 + lx] = sg;
        }
    }
}

// ---------------------------------------------------------------------------
extern "C" void kernel_launch(void* const* d_in, const int* in_sizes, int n_in,
                              void* d_out, int out_size) {
    const float* x  = (const float*)d_in[0];
    const float* cw = (const float*)d_in[1];
    const float* cb = (const float*)d_in[2];
    float* out = (float*)d_out;

    reset_kernel<<<1, 1>>>();
    // step 0: pool(0) + conv(0), no mul
    step_kernel<<<NPOOL + NCONV, 256>>>(x, out, cw, cb, 0, 0, NPOOL, 0);
    // steps 1..7: pool(s)+conv(s) overlapped with mul(s-1)
    for (int s = 1; s < B; ++s)
        step_kernel<<<NPOOL + NMUL + NCONV, 256>>>(x, out, cw, cb, s, s - 1,
                                                   NPOOL, NMUL);
    // final: mul(7) only
    step_kernel<<<NMUL, 256>>>(x, out, cw, cb, 0, B - 1, 0, NMUL);
}

// round 12
// speedup vs baseline: 1.6961x; 1.6961x over previous
#include <cuda_runtime.h>
#include <cstdint>

#define B 8
#define C 128
#define H 256
#define W 256
#define HW (H*W)        // 65536
#define HW4 (HW/4)      // 16384

__device__ float g_pooled[B * HW];
__device__ float g_attn[B * HW];

// ---------------------------------------------------------------------------
// Kernel 1: pooled[b,h,w] = max_c x[b,c,h,w]   (R1 shape: 512 blocks,
// one thread per float4-pixel, 128-channel loop -> 6.1 TB/s measured).
// Cache policy: batches 0..4 evict-first (__ldcs), 5..7 default -> at kernel
// end L2 retains x5,x6,x7 (~100MB) for the mul kernel.
// ---------------------------------------------------------------------------
__global__ void __launch_bounds__(256) pool_max_kernel(const float* __restrict__ x) {
    int t = blockIdx.x * blockDim.x + threadIdx.x;   // < B*HW4
    int b   = t >> 14;
    int hw4 = t & (HW4 - 1);
    const float4* p = reinterpret_cast<const float4*>(x) + (size_t)b * C * HW4 + hw4;

    float4 m = make_float4(-3.4e38f, -3.4e38f, -3.4e38f, -3.4e38f);
    if (b < 5) {
        #pragma unroll 4
        for (int c = 0; c < C; ++c) {
            float4 v = __ldcs(p + (size_t)c * HW4);   // read-once, evict-first
            m.x = fmaxf(m.x, v.x);
            m.y = fmaxf(m.y, v.y);
            m.z = fmaxf(m.z, v.z);
            m.w = fmaxf(m.w, v.w);
        }
    } else {
        #pragma unroll 4
        for (int c = 0; c < C; ++c) {
            float4 v = p[(size_t)c * HW4];            // default: stays in L2
            m.x = fmaxf(m.x, v.x);
            m.y = fmaxf(m.y, v.y);
            m.z = fmaxf(m.z, v.z);
            m.w = fmaxf(m.w, v.w);
        }
    }
    reinterpret_cast<float4*>(g_pooled)[t] = m;
}

// ---------------------------------------------------------------------------
// Kernel 2: attn = sigmoid(conv7x7(pooled) + bias), zero pad 3. (R1 shape)
// ---------------------------------------------------------------------------
#define TW 64
#define TH 16

__global__ void __launch_bounds__(256) conv_sigmoid_kernel(
        const float* __restrict__ cw, const float* __restrict__ cb) {
    __shared__ float s[TH + 6][TW + 8];
    const int b   = blockIdx.z;
    const int tx0 = blockIdx.x * TW;
    const int ty0 = blockIdx.y * TH;
    const float* pb = g_pooled + b * HW;

    for (int i = threadIdx.x; i < (TH + 6) * (TW + 6); i += 256) {
        int ly = i / (TW + 6);
        int lx = i - ly * (TW + 6);
        int gy = ty0 + ly - 3;
        int gx = tx0 + lx - 3;
        float v = 0.0f;
        if (gy >= 0 && gy < H && gx >= 0 && gx < W) v = pb[gy * W + gx];
        s[ly][lx] = v;
    }
    __syncthreads();

    float wr[49];
    #pragma unroll
    for (int i = 0; i < 49; ++i) wr[i] = __ldg(&cw[i]);
    const float bias = __ldg(&cb[0]);

    const int lx  = threadIdx.x & (TW - 1);
    const int ly0 = threadIdx.x >> 6;

    #pragma unroll
    for (int r = 0; r < TH; r += 4) {
        const int ly = ly0 + r;
        float acc = bias;
        #pragma unroll
        for (int i = 0; i < 7; ++i)
            #pragma unroll
            for (int j = 0; j < 7; ++j)
                acc = fmaf(s[ly + i][lx + j], wr[i * 7 + j], acc);
        float sg = 1.0f / (1.0f + __expf(-acc));
        g_attn[b * HW + (ty0 + ly) * W + tx0 + lx] = sg;
    }
}

// ---------------------------------------------------------------------------
// Kernel 3: out = x * attn (R1 shape: one float4/thread, 65536 blocks),
// batches iterated in REVERSE so the first reads (b=7,6,5) hit the L2
// leftovers from the pool kernel. __ldcs on x, __stcs on out.
// ---------------------------------------------------------------------------
__global__ void __launch_bounds__(256) mul_kernel(
        const float* __restrict__ x, float* __restrict__ out) {
    size_t i = (size_t)blockIdx.x * blockDim.x + threadIdx.x;   // float4 index
    int bi  = (int)(i >> 21);                 // i / (C*HW4)
    int rb  = (B - 1) - bi;                   // reversed batch
    size_t off = i & ((1u << 21) - 1);        // within-batch f4 offset
    int hw4 = (int)(off & (HW4 - 1));
    size_t gi = ((size_t)rb << 21) + off;

    float4 a = __ldg(reinterpret_cast<const float4*>(g_attn) + (size_t)rb * HW4 + hw4);
    float4 v = __ldcs(reinterpret_cast<const float4*>(x) + gi);
    v.x *= a.x; v.y *= a.y; v.z *= a.z; v.w *= a.w;
    __stcs(reinterpret_cast<float4*>(out) + gi, v);
}

// ---------------------------------------------------------------------------
extern "C" void kernel_launch(void* const* d_in, const int* in_sizes, int n_in,
                              void* d_out, int out_size) {
    const float* x  = (const float*)d_in[0];
    const float* cw = (const float*)d_in[1];
    const float* cb = (const float*)d_in[2];
    float* out = (float*)d_out;

    pool_max_kernel<<<(B * HW4) / 256, 256>>>(x);
    dim3 g2(W / TW, H / TH, B);
    conv_sigmoid_kernel<<<g2, 256>>>(cw, cb);
    mul_kernel<<<(size_t)(B * C * HW4) / 256, 256>>>(x, out);
}